// round 4
// baseline (speedup 1.0000x reference)
#include <cuda_runtime.h>
#include <math.h>

// ----------------------------------------------------------------------------
// margin ranking loss (all i<j pairs) + weighted BCE, B=8192, labels in {0,1}.
//   equal-label pairs: contribute relu(m) each -> closed form from n1
//   mixed pairs:       relu(m - p_pos + p_neg) -> n1*n0 scalar relu-adds
// out[0] = (relu(m)*eqPairs + sum_mixed)/B ; out[1] = mean weighted BCE
// ----------------------------------------------------------------------------

#define KA_T 256
#define K2_T 256
#define MAXB 8192
#define GX   8          // pos-side blocks (8 * 512 = 4096 pos per sweep)
#define GY   37         // neg-side slices  -> 296 blocks = 2 per SM
#define REG  2          // pos values per thread, in registers
#define TILE_MAX 232    // >= ceil(MAXB/GY) + pad
#define NSLOT 32
#define SLOTSTRIDE 16   // doubles -> 128B stride (defeats L2 hash pairing)

// scratch (allocation-free rule: __device__ globals)
__device__ float    g_pos[MAXB];
__device__ float    g_neg[MAXB];
__device__ int      g_posCnt = 0;
__device__ int      g_negCnt = 0;
__device__ double   g_bceArr[NSLOT * SLOTSTRIDE];
__device__ double   g_mixArr[NSLOT * SLOTSTRIDE];
__device__ unsigned g_done2  = 0;

__device__ __forceinline__ float read_margin(const void* p) {
    if (p == nullptr) return 1.0f;
    int v = *(const int*)p;
    if (v >= -1000000 && v <= 1000000) return (float)v;   // int scalar
    return __int_as_float(v);                             // float bits
}

// ---------------------------------------------------------------------------
// Kernel A: 32 blocks x 256.
//  - per-thread BCE -> warp shfl -> block smem reduce -> 1 slot-atomic/block
//  - warp ballot compaction + per-warp atomic segment reservation -> scatter
// ---------------------------------------------------------------------------
__global__ void __launch_bounds__(KA_T)
kA(const float* __restrict__ preds,
   const float* __restrict__ labels,
   const float* __restrict__ logits,
   const float* __restrict__ targets,
   const float* __restrict__ pw_,
   int n)
{
    const int tid  = threadIdx.x;
    const int i    = blockIdx.x * KA_T + tid;
    const int lane = tid & 31, wid = tid >> 5;
    const bool inb = (i < n);

    float p = 0.0f, bce = 0.0f;
    bool flag = false;
    if (inb) {
        p    = preds[i];
        flag = (labels[i] > 0.5f);
        const float x  = logits[i];
        const float t  = targets[i];
        const float pw = pw_[0];
        const float mv = fmaxf(-x, 0.0f);
        const float sp = __logf(__expf(-mv) + __expf(-x - mv)) + mv;  // softplus(-x)
        bce = (1.0f - t) * x + (1.0f + (pw - 1.0f) * t) * sp;
    }

    // warp compaction + per-warp segment reservation (sums are commutative;
    // atomic ordering jitter ~1e-9 rel << 1e-3 tol)
    const unsigned bm   = __ballot_sync(0xffffffffu, flag && inb);
    const unsigned vm   = __ballot_sync(0xffffffffu, inb);
    const int      rank = __popc(bm & ((1u << lane) - 1u));
    const int      c    = __popc(bm);
    const int      v    = __popc(vm);
    int bp = 0, bn = 0;
    if (lane == 0) {
        bp = atomicAdd(&g_posCnt, c);
        bn = atomicAdd(&g_negCnt, v - c);
    }
    bp = __shfl_sync(0xffffffffu, bp, 0);
    bn = __shfl_sync(0xffffffffu, bn, 0);
    if (inb) {
        if (flag) g_pos[bp + rank] = p;
        else      g_neg[bn + (__popc(vm & ((1u << lane) - 1u)) - rank)] = p;
    }

    // BCE: warp shfl -> block reduce -> ONE atomic per block to a unique slot
    float w = bce;
    #pragma unroll
    for (int off = 16; off; off >>= 1)
        w += __shfl_down_sync(0xffffffffu, w, off);
    __shared__ double wsum[8];
    if (lane == 0) wsum[wid] = (double)w;
    __syncthreads();
    if (tid == 0) {
        double b = 0.0;
        #pragma unroll
        for (int k = 0; k < 8; k++) b += wsum[k];
        atomicAdd(&g_bceArr[(blockIdx.x & (NSLOT - 1)) * SLOTSTRIDE], b);
    }
}

// ---------------------------------------------------------------------------
// Kernel 2: GX x GY = 296 blocks x 256 (2 per SM, balanced).
//  y: 1/GY slice of neg, cached in smem pre-added with margin (poison -1e30).
//  x: REG=2 pos per thread in registers (poison +1e30), grid-stride sweep.
//  Inner: float4 smem loads, tree-summed relu terms, 1 dep-add per acc/group.
//  Last block: finalize out[0], out[1], reset all accumulators.
// ---------------------------------------------------------------------------
__global__ void __launch_bounds__(K2_T)
k2(int n, const void* __restrict__ marginp, float* __restrict__ out)
{
    const int tid = threadIdx.x;
    const float m = read_margin(marginp);
    const int n1 = g_posCnt;
    const int n0 = n - n1;

    // neg slice -> smem (pre-add margin)
    const int nchunk = (n0 + GY - 1) / GY;
    const int ns   = blockIdx.y * nchunk;
    const int cnt  = max(min(ns + nchunk, n0) - ns, 0);
    const int cnt4 = (cnt + 3) & ~3;

    __shared__ __align__(16) float tile[TILE_MAX];
    for (int i = tid; i < cnt4; i += K2_T)
        tile[i] = (i < cnt) ? (m + g_neg[ns + i]) : -1e30f;
    __syncthreads();

    double accd = 0.0;
    {
        float s0 = 0.f, s1 = 0.f;
        for (int pb = blockIdx.x * (K2_T * REG); pb < n1; pb += GX * K2_T * REG) {
            const int i0 = pb + tid;
            const float a0 = (i0         < n1) ? g_pos[i0]         : 1e30f;
            const float a1 = (i0 + K2_T < n1) ? g_pos[i0 + K2_T]  : 1e30f;
            for (int i = 0; i < cnt4; i += 4) {
                const float4 t = *(const float4*)&tile[i];
                s0 += (fmaxf(t.x - a0, 0.f) + fmaxf(t.y - a0, 0.f))
                    + (fmaxf(t.z - a0, 0.f) + fmaxf(t.w - a0, 0.f));
                s1 += (fmaxf(t.x - a1, 0.f) + fmaxf(t.y - a1, 0.f))
                    + (fmaxf(t.z - a1, 0.f) + fmaxf(t.w - a1, 0.f));
            }
        }
        accd = (double)(s0 + s1);
    }

    // warp shfl fp64 -> block smem -> ONE spread-slot atomic per block
    const int lane = tid & 31, wid = tid >> 5;
    #pragma unroll
    for (int off = 16; off; off >>= 1)
        accd += __shfl_down_sync(0xffffffffu, accd, off);
    __shared__ double wsum[8];
    if (lane == 0) wsum[wid] = accd;
    __syncthreads();
    if (tid == 0) {
        double b = 0.0;
        #pragma unroll
        for (int w2 = 0; w2 < 8; w2++) b += wsum[w2];
        const int bid = blockIdx.y * GX + blockIdx.x;
        atomicAdd(&g_mixArr[(bid & (NSLOT - 1)) * SLOTSTRIDE], b);
        __threadfence();
        const unsigned prev = atomicAdd(&g_done2, 1u);
        if (prev == (unsigned)(GX * GY) - 1u) {
            double mix = 0.0, bsum = 0.0;
            #pragma unroll
            for (int s = 0; s < NSLOT; s++) {
                mix  += g_mixArr[s * SLOTSTRIDE];
                bsum += g_bceArr[s * SLOTSTRIDE];
            }
            const double dn1 = (double)n1, dn0 = (double)n0;
            const double eqPairs = 0.5 * (dn1 * (dn1 - 1.0) + dn0 * (dn0 - 1.0));
            const double mm = (double)fmaxf(m, 0.0f);
            out[0] = (float)((mm * eqPairs + mix) / (double)n);
            out[1] = (float)(bsum / (double)n);
            // reset for next graph replay
            #pragma unroll
            for (int s = 0; s < NSLOT; s++) {
                g_mixArr[s * SLOTSTRIDE] = 0.0;
                g_bceArr[s * SLOTSTRIDE] = 0.0;
            }
            g_posCnt = 0; g_negCnt = 0; g_done2 = 0u;
        }
    }
}

// ---------------------------------------------------------------------------
extern "C" void kernel_launch(void* const* d_in, const int* in_sizes, int n_in,
                              void* d_out, int out_size)
{
    const float* preds   = (const float*)d_in[0];
    const float* labels  = (const float*)d_in[1];
    const float* logits  = (const float*)d_in[2];
    const float* targets = (const float*)d_in[3];
    const float* pw      = (const float*)d_in[4];
    const void*  marginp = (n_in >= 6) ? d_in[5] : nullptr;
    const int n = in_sizes[0];
    float* out = (float*)d_out;

    kA<<<(n + KA_T - 1) / KA_T, KA_T>>>(preds, labels, logits, targets, pw, n);
    k2<<<dim3(GX, GY), K2_T>>>(n, marginp, out);
}